// round 8
// baseline (speedup 1.0000x reference)
#include <cuda_runtime.h>
#include <cuda_bf16.h>
#include <cstdint>

// ---------------- problem constants ----------------
#define AA 64
#define MSEQ 128
#define DD 128
#define MMI 127

#define NPAIR_TRI 2080
#define NP (2*NPAIR_TRI + AA*AA)          // 8256 pair-blocks

// ---------------- device scratch (no allocs) ----------------
// bf16 hi/lo increment tiles: [tsr(2)][seq(64)][row(128)][col(128)]
__device__ __align__(16) __nv_bfloat16 g_hi[2*64*128*128];   // 4 MB
__device__ __align__(16) __nv_bfloat16 g_lo[2*64*128*128];   // 4 MB
__device__ float g_partials[NP];

// ---------------- smem byte map (block kernel) ----------------
// GEMM phase: 4 chunk buffers, 128 rows x 144B (64 bf16 + 8 pad)
#define ROWB 144
#define SM_A_HI 0
#define SM_A_LO 18432
#define SM_B_HI 36864
#define SM_B_LO 55296
#define SMEM_BYTES 73728
// PDE phase (aliases buffers): sM = (M-1), fp32, 128 x SM_STRIDE; then ring
#define SM_STRIDE 130
#define RING_OFF 16640                    // float idx; 32-slot warp-boundary ring

// PDE wavefront parameters
#define PDE_E 10                          // warp1 extra lag (steps)
#define PDE_T 328                         // 41 epochs x 8 steps (last result at t=326)

__device__ __forceinline__ uint32_t smem_u32(const void* p) {
    uint32_t a;
    asm("{ .reg .u64 t; cvta.to.shared.u64 t, %1; cvt.u32.u64 %0, t; }" : "=r"(a) : "l"(p));
    return a;
}

__device__ __forceinline__ void ldsm4(uint32_t* r, uint32_t addr) {
    asm volatile("ldmatrix.sync.aligned.m8n8.x4.shared.b16 {%0,%1,%2,%3}, [%4];"
        : "=r"(r[0]), "=r"(r[1]), "=r"(r[2]), "=r"(r[3]) : "r"(addr));
}

__device__ __forceinline__ void mma16816(float* c, const uint32_t* a,
                                         uint32_t b0, uint32_t b1) {
    asm volatile(
        "mma.sync.aligned.m16n8k16.row.col.f32.bf16.bf16.f32 "
        "{%0,%1,%2,%3}, {%4,%5,%6,%7}, {%8,%9}, {%0,%1,%2,%3};"
        : "+f"(c[0]), "+f"(c[1]), "+f"(c[2]), "+f"(c[3])
        : "r"(a[0]), "r"(a[1]), "r"(a[2]), "r"(a[3]), "r"(b0), "r"(b1));
}

// ---------------- precompute: bf16 hi/lo increments ----------------
__global__ __launch_bounds__(256)
void sig_precompute_kernel(const float* __restrict__ X, const float* __restrict__ Y) {
    const int blk = blockIdx.x;                 // tsr*64 + seq
    const int seq = blk & 63;
    const int tsr = blk >> 6;
    const float* src = (tsr ? Y : X) + (size_t)seq * MSEQ * DD;
    __nv_bfloat16* hi = g_hi + (size_t)blk * 128 * 128;
    __nv_bfloat16* lo = g_lo + (size_t)blk * 128 * 128;

    const int tid = threadIdx.x;
#pragma unroll
    for (int i = 0; i < 16; ++i) {
        int idx = tid + i * 256;                // 0..4095 float4 groups
        int r  = idx >> 5;
        int c4 = (idx & 31) << 2;
        float4 cur = *reinterpret_cast<const float4*>(src + r * DD + c4);
        float4 nxt = (r < MMI) ? *reinterpret_cast<const float4*>(src + (r + 1) * DD + c4) : cur;
        float i0 = nxt.x - cur.x, i1 = nxt.y - cur.y, i2 = nxt.z - cur.z, i3 = nxt.w - cur.w;
        __nv_bfloat16 h0 = __float2bfloat16(i0), h1 = __float2bfloat16(i1);
        __nv_bfloat16 h2 = __float2bfloat16(i2), h3 = __float2bfloat16(i3);
        __nv_bfloat16 l0 = __float2bfloat16(i0 - __bfloat162float(h0));
        __nv_bfloat16 l1 = __float2bfloat16(i1 - __bfloat162float(h1));
        __nv_bfloat16 l2 = __float2bfloat16(i2 - __bfloat162float(h2));
        __nv_bfloat16 l3 = __float2bfloat16(i3 - __bfloat162float(h3));
        __nv_bfloat162 hp0(h0, h1), hp1(h2, h3), lp0(l0, l1), lp1(l2, l3);
        uint2 hv, lv;
        hv.x = *reinterpret_cast<uint32_t*>(&hp0); hv.y = *reinterpret_cast<uint32_t*>(&hp1);
        lv.x = *reinterpret_cast<uint32_t*>(&lp0); lv.y = *reinterpret_cast<uint32_t*>(&lp1);
        *reinterpret_cast<uint2*>(hi + r * 128 + c4) = hv;
        *reinterpret_cast<uint2*>(lo + r * 128 + c4) = lv;
    }
}

// ---------------- fused per-pair kernel ----------------
__global__ __launch_bounds__(256, 2)
void sig_block_kernel() {
    extern __shared__ unsigned char smem[];
    const uint32_t sbase = smem_u32(smem);
    const int bid = blockIdx.x;
    const int tid = threadIdx.x;
    const int wid = tid >> 5, lane = tid & 31;

    // ---- decode (gram type, pair) ----
    int g, a, b;
    float w;
    if (bid < 2 * NPAIR_TRI) {
        g = (bid < NPAIR_TRI) ? 0 : 1;
        int t = bid - g * NPAIR_TRI;
        int aa = 0;
        while (t >= (AA - aa)) { t -= (AA - aa); ++aa; }
        a = aa; b = aa + t;
        w = (a == b) ? 1.0f : 2.0f;
    } else {
        g = 2;
        int t = bid - 2 * NPAIR_TRI;
        a = t >> 6; b = t & 63;
        w = -2.0f;
    }
    const int idxA = ((g == 1) ? 64 : 0) + a;     // Y for YY else X
    const int idxB = ((g == 0) ? 0 : 64) + b;     // X for XX else Y
    const __nv_bfloat16* gAh = g_hi + (size_t)idxA * 16384;
    const __nv_bfloat16* gAl = g_lo + (size_t)idxA * 16384;
    const __nv_bfloat16* gBh = g_hi + (size_t)idxB * 16384;
    const __nv_bfloat16* gBl = g_lo + (size_t)idxB * 16384;

    // ---- per-thread ldmatrix address offsets ----
    const int ablk = lane >> 3;
    const int arow = ((ablk & 1) << 3) + (lane & 7);
    const uint32_t aoff = (uint32_t)((16 * wid + arow) * ROWB + ((ablk >> 1) << 4));
    const int bblk = lane >> 3;
    const uint32_t boff = (uint32_t)((((bblk >> 1) << 3) + (lane & 7)) * ROWB + ((bblk & 1) << 4));

    float acc[64];
#pragma unroll
    for (int i = 0; i < 64; ++i) acc[i] = 0.0f;

#pragma unroll
    for (int kc = 0; kc < 2; ++kc) {
        if (kc) __syncthreads();   // chunk0 fragment reads done before overwrite

        // ---- cooperative load of 4 chunk buffers (coalesced 128B rows) ----
#pragma unroll
        for (int i = 0; i < 4; ++i) {
            int idx = tid + i * 256;            // 0..1023 16B-chunks per buffer
            int r = idx >> 3, c = idx & 7;
            size_t go = (size_t)r * 128 + kc * 64 + c * 8;   // bf16 elems
            uint32_t so = (uint32_t)(r * ROWB + c * 16);
            *reinterpret_cast<uint4*>(smem + SM_A_HI + so) = *reinterpret_cast<const uint4*>(gAh + go);
            *reinterpret_cast<uint4*>(smem + SM_A_LO + so) = *reinterpret_cast<const uint4*>(gAl + go);
            *reinterpret_cast<uint4*>(smem + SM_B_HI + so) = *reinterpret_cast<const uint4*>(gBh + go);
            *reinterpret_cast<uint4*>(smem + SM_B_LO + so) = *reinterpret_cast<const uint4*>(gBl + go);
        }
        __syncthreads();

        // ---- warp GEMM: m16 x n128, k=64 in 4 k16 steps, 3-term bf16 split ----
#pragma unroll
        for (int kk = 0; kk < 4; ++kk) {
            uint32_t ah[4], al[4];
            ldsm4(ah, sbase + SM_A_HI + aoff + kk * 32);
            ldsm4(al, sbase + SM_A_LO + aoff + kk * 32);
#pragma unroll
            for (int j2 = 0; j2 < 8; ++j2) {
                uint32_t bh[4], bl[4];
                uint32_t bo = boff + j2 * (16 * ROWB) + kk * 32;
                ldsm4(bh, sbase + SM_B_HI + bo);
                ldsm4(bl, sbase + SM_B_LO + bo);
                float* c0 = acc + (2 * j2) * 4;
                float* c1 = acc + (2 * j2 + 1) * 4;
                mma16816(c0, ah, bh[0], bh[1]);   // hi*hi
                mma16816(c0, ah, bl[0], bl[1]);   // hi*lo
                mma16816(c0, al, bh[0], bh[1]);   // lo*hi
                mma16816(c1, ah, bh[2], bh[3]);
                mma16816(c1, ah, bl[2], bl[3]);
                mma16816(c1, al, bh[2], bh[3]);
            }
        }
    }
    __syncthreads();   // all fragment reads done; safe to overwrite with sM

    // ---- epilogue: acc-1 -> sM (fp32, stride 130) ----
    float* sM = reinterpret_cast<float*>(smem);
    {
        const int r0 = 16 * wid + (lane >> 2);
        const int cb = (lane & 3) << 1;
#pragma unroll
        for (int j = 0; j < 16; ++j) {
            float* c = acc + j * 4;
            *reinterpret_cast<float2*>(&sM[r0 * SM_STRIDE + 8 * j + cb])
                = make_float2(c[0] - 1.0f, c[1] - 1.0f);
            *reinterpret_cast<float2*>(&sM[(r0 + 8) * SM_STRIDE + 8 * j + cb])
                = make_float2(c[2] - 1.0f, c[3] - 1.0f);
        }
    }
    __syncthreads();

    // ---- PDE: skewed register wavefront ----
    // K[p][q] = K[p][q-1] + K[p-1][q] + K[p-1][q-1]*(M[p-1][q-1]-1), K[0][*]=K[*][0]=1
    // Thread r<64 owns rows p1=2r+1, p2=2r+2. At step t it computes
    // (p1, q1=t-off) and (p2, q1-1), off = 3r (+E for warp 1).
    // Neighbor row p1-1=2r is thread r-1's p2: its export at step s is
    // sv_s = K[2r][s-3(r-1)-1] = K[2r][s-3r+2], so
    //   K[p1-1][q1]   = sv_{t-2}   (s-3r+2 = t-3r  => s = t-2)
    //   K[p1-1][q1-1] = sv_{t-3}
    // (inactive producers keep b0 = 1 = K[.][0], matching the boundary).
    // Warp0->warp1 crosses via smem ring with lag E; sync every 8 steps.
    float* ring = sM + RING_OFF;          // 32 floats
    if (tid < 32) ring[tid] = 1.0f;
    __syncthreads();

    const int off = 3 * tid + ((tid >= 32) ? PDE_E : 0);
    const int base = 260 * tid - off - 1;  // m1 idx = base + t (stride 257 over lanes: conflict-free)

    float a0 = 1.0f, a1 = 1.0f, b0 = 1.0f;
    float h0 = 1.0f, h1 = 1.0f, h2r = 1.0f, h3r = 1.0f;  // h[s&3] = sv_s, unrolled
    float res = 0.0f;

    for (int epoch = 0; epoch < PDE_T / 8; ++epoch) {
        if (tid < 64) {
            const int t0 = epoch * 8 + 1;
#pragma unroll
            for (int u = 0; u < 8; ++u) {
                const int t = t0 + u;
                // t == u+1 (mod 4):  (t-2)&3 = (u+3)&3,  (t-3)&3 = (u+2)&3
                float g2, g3;
                {
                    const int s1 = (u + 3) & 3;   // slot of sv_{t-2} = K[p1-1][q1]
                    const int s2 = (u + 2) & 3;   // slot of sv_{t-3} = K[p1-1][q1-1]
                    g2 = (s1 == 0) ? h0 : (s1 == 1) ? h1 : (s1 == 2) ? h2r : h3r;
                    g3 = (s2 == 0) ? h0 : (s2 == 1) ? h1 : (s2 == 2) ? h2r : h3r;
                }
                const int q1 = t - off;
                const float m1 = sM[base + t];          // (M-1)[p1-1][q1-1]
                const float m2 = sM[base + t + 129];    // (M-1)[p2-1][q1-2]

                const float v1 = a0 + g2 + g3 * m1;     // K[p1][q1]
                const float v2 = b0 + a0 + a1 * m2;     // K[p2][q1-1]

                const bool act1 = (q1 >= 1) && (q1 <= 127);
                const bool act2 = (q1 >= 2) && (q1 <= 128) && (tid < 63);
                if (act1) { a1 = a0; a0 = v1; if (q1 == 127) res = v1; }
                if (act2) { b0 = v2; }

                // export neighbor value: sv_t = b0 after this step (frozen = boundary 1)
                float sv = __shfl_up_sync(0xffffffffu, b0, 1);
                if (tid == 0)  sv = 1.0f;                       // row 0 boundary
                if (tid == 32) sv = ring[(t - PDE_E) & 31];     // warp0->warp1
                {
                    const int sw = (u + 1) & 3;   // t&3
                    if (sw == 0) h0 = sv; else if (sw == 1) h1 = sv;
                    else if (sw == 2) h2r = sv; else h3r = sv;
                }
                if (tid == 31) ring[t & 31] = b0;
            }
        }
        __syncthreads();
    }

    if (tid == 63) g_partials[bid] = w * res;
}

// ---------------- deterministic FP64 reduction ----------------
__global__ void sig_reduce_kernel(float* __restrict__ out) {
    __shared__ double sh[256];
    const int tid = threadIdx.x;
    double acc = 0.0;
    for (int i = tid; i < NP; i += 256) acc += (double)g_partials[i];
    sh[tid] = acc;
    __syncthreads();
    for (int s = 128; s > 0; s >>= 1) {
        if (tid < s) sh[tid] += sh[tid + s];
        __syncthreads();
    }
    if (tid == 0) out[0] = (float)(sh[0] * (1.0 / 4096.0));
}

extern "C" void kernel_launch(void* const* d_in, const int* in_sizes, int n_in,
                              void* d_out, int out_size) {
    const float* X = (const float*)d_in[0];
    const float* Y = (const float*)d_in[1];
    float* out = (float*)d_out;

    cudaFuncSetAttribute(sig_block_kernel,
                         cudaFuncAttributeMaxDynamicSharedMemorySize, SMEM_BYTES);

    sig_precompute_kernel<<<128, 256>>>(X, Y);
    sig_block_kernel<<<NP, 256, SMEM_BYTES>>>();
    sig_reduce_kernel<<<1, 256>>>(out);
}

// round 9
// speedup vs baseline: 1.7800x; 1.7800x over previous
#include <cuda_runtime.h>
#include <cuda_bf16.h>
#include <cstdint>

// ---------------- problem constants ----------------
#define AA 64
#define MSEQ 128
#define DD 128
#define MMI 127

#define NPAIR_TRI 2080
#define NP (2*NPAIR_TRI + AA*AA)          // 8256 pair-blocks

// ---------------- device scratch (no allocs) ----------------
// bf16 hi/lo increment tiles: [tsr(2)][seq(64)][row(128)][col(128)]
__device__ __align__(16) __nv_bfloat16 g_hi[2*64*128*128];   // 4 MB
__device__ __align__(16) __nv_bfloat16 g_lo[2*64*128*128];   // 4 MB
__device__ float g_partials[NP];

// ---------------- smem byte map (block kernel) ----------------
// GEMM phase: 4 chunk buffers, 128 rows x 144B (64 bf16 + 8 pad)
#define ROWB 144
#define SM_A_HI 0
#define SM_A_LO 18432
#define SM_B_HI 36864
#define SM_B_LO 55296
#define SMEM_BYTES 73728
// PDE phase (aliases buffers): sM = (M-1), fp32, 128 x SM_STRIDE
#define SM_STRIDE 130

__device__ __forceinline__ uint32_t smem_u32(const void* p) {
    uint32_t a;
    asm("{ .reg .u64 t; cvta.to.shared.u64 t, %1; cvt.u32.u64 %0, t; }" : "=r"(a) : "l"(p));
    return a;
}

__device__ __forceinline__ void ldsm4(uint32_t* r, uint32_t addr) {
    asm volatile("ldmatrix.sync.aligned.m8n8.x4.shared.b16 {%0,%1,%2,%3}, [%4];"
        : "=r"(r[0]), "=r"(r[1]), "=r"(r[2]), "=r"(r[3]) : "r"(addr));
}

__device__ __forceinline__ void mma16816(float* c, const uint32_t* a,
                                         uint32_t b0, uint32_t b1) {
    asm volatile(
        "mma.sync.aligned.m16n8k16.row.col.f32.bf16.bf16.f32 "
        "{%0,%1,%2,%3}, {%4,%5,%6,%7}, {%8,%9}, {%0,%1,%2,%3};"
        : "+f"(c[0]), "+f"(c[1]), "+f"(c[2]), "+f"(c[3])
        : "r"(a[0]), "r"(a[1]), "r"(a[2]), "r"(a[3]), "r"(b0), "r"(b1));
}

// ---------------- precompute: bf16 hi/lo increments ----------------
__global__ __launch_bounds__(256)
void sig_precompute_kernel(const float* __restrict__ X, const float* __restrict__ Y) {
    const int blk = blockIdx.x;                 // tsr*64 + seq
    const int seq = blk & 63;
    const int tsr = blk >> 6;
    const float* src = (tsr ? Y : X) + (size_t)seq * MSEQ * DD;
    __nv_bfloat16* hi = g_hi + (size_t)blk * 128 * 128;
    __nv_bfloat16* lo = g_lo + (size_t)blk * 128 * 128;

    const int tid = threadIdx.x;
#pragma unroll
    for (int i = 0; i < 16; ++i) {
        int idx = tid + i * 256;                // 0..4095 float4 groups
        int r  = idx >> 5;
        int c4 = (idx & 31) << 2;
        float4 cur = *reinterpret_cast<const float4*>(src + r * DD + c4);
        float4 nxt = (r < MMI) ? *reinterpret_cast<const float4*>(src + (r + 1) * DD + c4) : cur;
        float i0 = nxt.x - cur.x, i1 = nxt.y - cur.y, i2 = nxt.z - cur.z, i3 = nxt.w - cur.w;
        __nv_bfloat16 h0 = __float2bfloat16(i0), h1 = __float2bfloat16(i1);
        __nv_bfloat16 h2 = __float2bfloat16(i2), h3 = __float2bfloat16(i3);
        __nv_bfloat16 l0 = __float2bfloat16(i0 - __bfloat162float(h0));
        __nv_bfloat16 l1 = __float2bfloat16(i1 - __bfloat162float(h1));
        __nv_bfloat16 l2 = __float2bfloat16(i2 - __bfloat162float(h2));
        __nv_bfloat16 l3 = __float2bfloat16(i3 - __bfloat162float(h3));
        __nv_bfloat162 hp0(h0, h1), hp1(h2, h3), lp0(l0, l1), lp1(l2, l3);
        uint2 hv, lv;
        hv.x = *reinterpret_cast<uint32_t*>(&hp0); hv.y = *reinterpret_cast<uint32_t*>(&hp1);
        lv.x = *reinterpret_cast<uint32_t*>(&lp0); lv.y = *reinterpret_cast<uint32_t*>(&lp1);
        *reinterpret_cast<uint2*>(hi + r * 128 + c4) = hv;
        *reinterpret_cast<uint2*>(lo + r * 128 + c4) = lv;
    }
}

// ---------------- fused per-pair kernel ----------------
__global__ __launch_bounds__(256, 2)
void sig_block_kernel() {
    extern __shared__ unsigned char smem[];
    const uint32_t sbase = smem_u32(smem);
    const int bid = blockIdx.x;
    const int tid = threadIdx.x;
    const int wid = tid >> 5, lane = tid & 31;

    // ---- decode (gram type, pair) ----
    int g, a, b;
    float w;
    if (bid < 2 * NPAIR_TRI) {
        g = (bid < NPAIR_TRI) ? 0 : 1;
        int t = bid - g * NPAIR_TRI;
        int aa = 0;
        while (t >= (AA - aa)) { t -= (AA - aa); ++aa; }
        a = aa; b = aa + t;
        w = (a == b) ? 1.0f : 2.0f;
    } else {
        g = 2;
        int t = bid - 2 * NPAIR_TRI;
        a = t >> 6; b = t & 63;
        w = -2.0f;
    }
    const int idxA = ((g == 1) ? 64 : 0) + a;     // Y for YY else X
    const int idxB = ((g == 0) ? 0 : 64) + b;     // X for XX else Y
    const __nv_bfloat16* gAh = g_hi + (size_t)idxA * 16384;
    const __nv_bfloat16* gAl = g_lo + (size_t)idxA * 16384;
    const __nv_bfloat16* gBh = g_hi + (size_t)idxB * 16384;
    const __nv_bfloat16* gBl = g_lo + (size_t)idxB * 16384;

    // ---- per-thread ldmatrix address offsets ----
    const int ablk = lane >> 3;
    const int arow = ((ablk & 1) << 3) + (lane & 7);
    const uint32_t aoff = (uint32_t)((16 * wid + arow) * ROWB + ((ablk >> 1) << 4));
    const int bblk = lane >> 3;
    const uint32_t boff = (uint32_t)((((bblk >> 1) << 3) + (lane & 7)) * ROWB + ((bblk & 1) << 4));

    float acc[64];
#pragma unroll
    for (int i = 0; i < 64; ++i) acc[i] = 0.0f;

#pragma unroll
    for (int kc = 0; kc < 2; ++kc) {
        if (kc) __syncthreads();   // chunk0 fragment reads done before overwrite

        // ---- cooperative load of 4 chunk buffers (coalesced 128B rows) ----
#pragma unroll
        for (int i = 0; i < 4; ++i) {
            int idx = tid + i * 256;            // 0..1023 16B-chunks per buffer
            int r = idx >> 3, c = idx & 7;
            size_t go = (size_t)r * 128 + kc * 64 + c * 8;   // bf16 elems
            uint32_t so = (uint32_t)(r * ROWB + c * 16);
            *reinterpret_cast<uint4*>(smem + SM_A_HI + so) = *reinterpret_cast<const uint4*>(gAh + go);
            *reinterpret_cast<uint4*>(smem + SM_A_LO + so) = *reinterpret_cast<const uint4*>(gAl + go);
            *reinterpret_cast<uint4*>(smem + SM_B_HI + so) = *reinterpret_cast<const uint4*>(gBh + go);
            *reinterpret_cast<uint4*>(smem + SM_B_LO + so) = *reinterpret_cast<const uint4*>(gBl + go);
        }
        __syncthreads();

        // ---- warp GEMM: m16 x n128, k=64 in 4 k16 steps, 3-term bf16 split ----
#pragma unroll
        for (int kk = 0; kk < 4; ++kk) {
            uint32_t ah[4], al[4];
            ldsm4(ah, sbase + SM_A_HI + aoff + kk * 32);
            ldsm4(al, sbase + SM_A_LO + aoff + kk * 32);
#pragma unroll
            for (int j2 = 0; j2 < 8; ++j2) {
                uint32_t bh[4], bl[4];
                uint32_t bo = boff + j2 * (16 * ROWB) + kk * 32;
                ldsm4(bh, sbase + SM_B_HI + bo);
                ldsm4(bl, sbase + SM_B_LO + bo);
                float* c0 = acc + (2 * j2) * 4;
                float* c1 = acc + (2 * j2 + 1) * 4;
                mma16816(c0, ah, bh[0], bh[1]);   // hi*hi
                mma16816(c0, ah, bl[0], bl[1]);   // hi*lo
                mma16816(c0, al, bh[0], bh[1]);   // lo*hi
                mma16816(c1, ah, bh[2], bh[3]);
                mma16816(c1, ah, bl[2], bl[3]);
                mma16816(c1, al, bh[2], bh[3]);
            }
        }
    }
    __syncthreads();   // all fragment reads done; safe to overwrite with sM

    // ---- epilogue: acc-1 -> sM (fp32, stride 130) ----
    float* sM = reinterpret_cast<float*>(smem);
    {
        const int r0 = 16 * wid + (lane >> 2);
        const int cb = (lane & 3) << 1;
#pragma unroll
        for (int j = 0; j < 16; ++j) {
            float* c = acc + j * 4;
            *reinterpret_cast<float2*>(&sM[r0 * SM_STRIDE + 8 * j + cb])
                = make_float2(c[0] - 1.0f, c[1] - 1.0f);
            *reinterpret_cast<float2*>(&sM[(r0 + 8) * SM_STRIDE + 8 * j + cb])
                = make_float2(c[2] - 1.0f, c[3] - 1.0f);
        }
    }
    __syncthreads();

    // ---- PDE: single-warp register wavefront, no barriers ----
    // K[p][q] = K[p][q-1] + K[p-1][q] + K[p-1][q-1]*(M-1)[p-1][q-1], K[0][*]=K[*][0]=1
    // Lane r owns rows p_i = 4r+1..4r+4. At anti-diagonal s (=p+q), row p computes
    // q = s-p. cur_i = K[p_i][s-1-p_i], pr_i = K[p_i][s-2-p_i] (1 before activation).
    // Row p_i-1 for i=0 is neighbor lane's row 4r -> shfl of (cur3, pr3); lane 0 = boundary 1.
    // Guards only needed pre-activation (s <= p_i); after s>=128 all real rows are
    // active and post-completion garbage (q>127) provably never reaches valid cells.
    // m addr = (4r+i)*130 + (s-p_i-1) = 516r + 129i + (s-2): in-bounds for all s in [2,254].
    if (wid == 0) {
        const float* mp = sM + 516 * lane - 2;   // mp[129*i + s]
        const int p1 = 4 * lane + 1, p2 = p1 + 1, p3 = p1 + 2, p4 = p1 + 3;
        float cur0 = 1.f, cur1 = 1.f, cur2 = 1.f, cur3 = 1.f;
        float pr0 = 1.f, pr1 = 1.f, pr2 = 1.f, pr3 = 1.f;

        // phase A: s = 2..127 (guarded commits)
#pragma unroll 2
        for (int s = 2; s <= 127; ++s) {
            float shc = __shfl_up_sync(0xffffffffu, cur3, 1);
            float shp = __shfl_up_sync(0xffffffffu, pr3, 1);
            if (lane == 0) { shc = 1.f; shp = 1.f; }
            const float m0 = mp[s];
            const float m1 = mp[129 + s];
            const float m2 = mp[258 + s];
            const float m3 = mp[387 + s];
            const float v0 = cur0 + shc  + shp * m0;
            const float v1 = cur1 + cur0 + pr0 * m1;
            const float v2 = cur2 + cur1 + pr1 * m2;
            const float v3 = cur3 + cur2 + pr2 * m3;
            if (s > p1) { pr0 = cur0; cur0 = v0; }
            if (s > p2) { pr1 = cur1; cur1 = v1; }
            if (s > p3) { pr2 = cur2; cur2 = v2; }
            if (s > p4) { pr3 = cur3; cur3 = v3; }
        }
        // phase B: s = 128..254 (unguarded; lane31 row128 free-runs harmless garbage)
#pragma unroll 2
        for (int s = 128; s <= 254; ++s) {
            float shc = __shfl_up_sync(0xffffffffu, cur3, 1);
            float shp = __shfl_up_sync(0xffffffffu, pr3, 1);
            if (lane == 0) { shc = 1.f; shp = 1.f; }
            const float m0 = mp[s];
            const float m1 = mp[129 + s];
            const float m2 = mp[258 + s];
            const float m3 = mp[387 + s];
            const float v0 = cur0 + shc  + shp * m0;
            const float v1 = cur1 + cur0 + pr0 * m1;
            const float v2 = cur2 + cur1 + pr1 * m2;
            const float v3 = cur3 + cur2 + pr2 * m3;
            pr0 = cur0; cur0 = v0;
            pr1 = cur1; cur1 = v1;
            pr2 = cur2; cur2 = v2;
            pr3 = cur3; cur3 = v3;
        }
        // K[127][127] = row 127 (lane 31, i=2) update at s=254
        if (lane == 31) g_partials[bid] = w * cur2;
    }
    // warps 1..7 simply exit (no further barriers; only warp 0 reads sM now)
}

// ---------------- deterministic FP64 reduction ----------------
__global__ void sig_reduce_kernel(float* __restrict__ out) {
    __shared__ double sh[256];
    const int tid = threadIdx.x;
    double acc = 0.0;
    for (int i = tid; i < NP; i += 256) acc += (double)g_partials[i];
    sh[tid] = acc;
    __syncthreads();
    for (int s = 128; s > 0; s >>= 1) {
        if (tid < s) sh[tid] += sh[tid + s];
        __syncthreads();
    }
    if (tid == 0) out[0] = (float)(sh[0] * (1.0 / 4096.0));
}

extern "C" void kernel_launch(void* const* d_in, const int* in_sizes, int n_in,
                              void* d_out, int out_size) {
    const float* X = (const float*)d_in[0];
    const float* Y = (const float*)d_in[1];
    float* out = (float*)d_out;

    cudaFuncSetAttribute(sig_block_kernel,
                         cudaFuncAttributeMaxDynamicSharedMemorySize, SMEM_BYTES);

    sig_precompute_kernel<<<128, 256>>>(X, Y);
    sig_block_kernel<<<NP, 256, SMEM_BYTES>>>();
    sig_reduce_kernel<<<1, 256>>>(out);
}

// round 12
// speedup vs baseline: 1.7974x; 1.0098x over previous
#include <cuda_runtime.h>
#include <cuda_bf16.h>
#include <cstdint>

// ---------------- problem constants ----------------
#define AA 64
#define MSEQ 128
#define DD 128
#define MMI 127

#define NPAIR_TRI 2080
#define NP (2*NPAIR_TRI + AA*AA)          // 8256 pair-blocks

// ---------------- device scratch (no allocs) ----------------
// bf16 hi/lo increment tiles: [tsr(2)][seq(64)][row(128)][col(128)]
__device__ __align__(16) __nv_bfloat16 g_hi[2*64*128*128];   // 4 MB
__device__ __align__(16) __nv_bfloat16 g_lo[2*64*128*128];   // 4 MB
__device__ float g_partials[NP];

// ---------------- smem byte map (block kernel) ----------------
// GEMM phase: cp.async double-buffered K-chunks of 32.
// Per chunk-set: A_hi, A_lo, B_hi, B_lo buffers of 128 rows x 80B
// (64B data + 16B pad; ldsm row banks {0,20,8,28,16,4,24,12}*4: conflict-free).
#define KC 32
#define ROWB 80
#define BUFB 10240                        // 128*80
#define SETB 40960                        // 4 buffers per set
#define SMEM_BYTES 81920                  // 2 sets; occ 2 (163KB/SM)
// PDE phase aliases buffers: sM = (M-1), fp32, 128 x SM_STRIDE (66560 B)
#define SM_STRIDE 130

__device__ __forceinline__ uint32_t smem_u32(const void* p) {
    uint32_t a;
    asm("{ .reg .u64 t; cvta.to.shared.u64 t, %1; cvt.u32.u64 %0, t; }" : "=r"(a) : "l"(p));
    return a;
}

__device__ __forceinline__ void ldsm4(uint32_t* r, uint32_t addr) {
    asm volatile("ldmatrix.sync.aligned.m8n8.x4.shared.b16 {%0,%1,%2,%3}, [%4];"
        : "=r"(r[0]), "=r"(r[1]), "=r"(r[2]), "=r"(r[3]) : "r"(addr));
}

__device__ __forceinline__ void mma16816(float* c, const uint32_t* a,
                                         uint32_t b0, uint32_t b1) {
    asm volatile(
        "mma.sync.aligned.m16n8k16.row.col.f32.bf16.bf16.f32 "
        "{%0,%1,%2,%3}, {%4,%5,%6,%7}, {%8,%9}, {%0,%1,%2,%3};"
        : "+f"(c[0]), "+f"(c[1]), "+f"(c[2]), "+f"(c[3])
        : "r"(a[0]), "r"(a[1]), "r"(a[2]), "r"(a[3]), "r"(b0), "r"(b1));
}

// ---------------- precompute: bf16 hi/lo increments ----------------
__global__ __launch_bounds__(256)
void sig_precompute_kernel(const float* __restrict__ X, const float* __restrict__ Y) {
    const int blk = blockIdx.x;                 // tsr*64 + seq
    const int seq = blk & 63;
    const int tsr = blk >> 6;
    const float* src = (tsr ? Y : X) + (size_t)seq * MSEQ * DD;
    __nv_bfloat16* hi = g_hi + (size_t)blk * 128 * 128;
    __nv_bfloat16* lo = g_lo + (size_t)blk * 128 * 128;

    const int tid = threadIdx.x;
#pragma unroll
    for (int i = 0; i < 16; ++i) {
        int idx = tid + i * 256;                // 0..4095 float4 groups
        int r  = idx >> 5;
        int c4 = (idx & 31) << 2;
        float4 cur = *reinterpret_cast<const float4*>(src + r * DD + c4);
        float4 nxt = (r < MMI) ? *reinterpret_cast<const float4*>(src + (r + 1) * DD + c4) : cur;
        float i0 = nxt.x - cur.x, i1 = nxt.y - cur.y, i2 = nxt.z - cur.z, i3 = nxt.w - cur.w;
        __nv_bfloat16 h0 = __float2bfloat16(i0), h1 = __float2bfloat16(i1);
        __nv_bfloat16 h2 = __float2bfloat16(i2), h3 = __float2bfloat16(i3);
        __nv_bfloat16 l0 = __float2bfloat16(i0 - __bfloat162float(h0));
        __nv_bfloat16 l1 = __float2bfloat16(i1 - __bfloat162float(h1));
        __nv_bfloat16 l2 = __float2bfloat16(i2 - __bfloat162float(h2));
        __nv_bfloat16 l3 = __float2bfloat16(i3 - __bfloat162float(h3));
        __nv_bfloat162 hp0(h0, h1), hp1(h2, h3), lp0(l0, l1), lp1(l2, l3);
        uint2 hv, lv;
        hv.x = *reinterpret_cast<uint32_t*>(&hp0); hv.y = *reinterpret_cast<uint32_t*>(&hp1);
        lv.x = *reinterpret_cast<uint32_t*>(&lp0); lv.y = *reinterpret_cast<uint32_t*>(&lp1);
        *reinterpret_cast<uint2*>(hi + r * 128 + c4) = hv;
        *reinterpret_cast<uint2*>(lo + r * 128 + c4) = lv;
    }
}

// ---------------- fused per-pair kernel ----------------
__global__ __launch_bounds__(256, 2)
void sig_block_kernel() {
    extern __shared__ unsigned char smem[];
    const uint32_t sbase = smem_u32(smem);
    const int bid = blockIdx.x;
    const int tid = threadIdx.x;
    const int wid = tid >> 5, lane = tid & 31;

    // ---- decode (gram type, pair) ----
    int g, a, b;
    float w;
    if (bid < 2 * NPAIR_TRI) {
        g = (bid < NPAIR_TRI) ? 0 : 1;
        int t = bid - g * NPAIR_TRI;
        int aa = 0;
        while (t >= (AA - aa)) { t -= (AA - aa); ++aa; }
        a = aa; b = aa + t;
        w = (a == b) ? 1.0f : 2.0f;
    } else {
        g = 2;
        int t = bid - 2 * NPAIR_TRI;
        a = t >> 6; b = t & 63;
        w = -2.0f;
    }
    const int idxA = ((g == 1) ? 64 : 0) + a;     // Y for YY else X
    const int idxB = ((g == 0) ? 0 : 64) + b;     // X for XX else Y
    const __nv_bfloat16* gAh = g_hi + (size_t)idxA * 16384;
    const __nv_bfloat16* gAl = g_lo + (size_t)idxA * 16384;
    const __nv_bfloat16* gBh = g_hi + (size_t)idxB * 16384;
    const __nv_bfloat16* gBl = g_lo + (size_t)idxB * 16384;

    // ---- warp tile: m32 x n64 (4 x 2 warp grid) ----
    const int mw = wid >> 1, nw = wid & 1;
    // A ldsm x4 blocks: 0:(m0-7,k0) 1:(m8-15,k0) 2:(m0-7,k8) 3:(m8-15,k8)
    const int ablk = lane >> 3;
    const int arow = ((ablk & 1) << 3) + (lane & 7);
    const uint32_t aoff = (uint32_t)((32 * mw + arow) * ROWB + ((ablk >> 1) << 4));
    // B ldsm x4 blocks: 0:(n0-7,k0) 1:(n0-7,k8) 2:(n8-15,k0) 3:(n8-15,k8)
    const int bblk = lane >> 3;
    const uint32_t boff = (uint32_t)((64 * nw + ((bblk >> 1) << 3) + (lane & 7)) * ROWB
                                     + ((bblk & 1) << 4));

    float acc[64];
#pragma unroll
    for (int i = 0; i < 64; ++i) acc[i] = 0.0f;

    // ---- cp.async chunk loader: 8 x 16B per thread per chunk ----
    auto issue_chunk = [&](int c, uint32_t setbase) {
#pragma unroll
        for (int j = 0; j < 8; ++j) {
            int idx = tid + j * 256;            // 0..2047
            int buf = idx >> 9;                 // 0..3
            int r   = (idx >> 2) & 127;
            int cc  = idx & 3;                  // 16B column within 64B row data
            uint32_t dst = sbase + setbase + buf * BUFB + (uint32_t)(r * ROWB + cc * 16);
            const __nv_bfloat16* gp = (buf == 0) ? gAh : (buf == 1) ? gAl
                                    : (buf == 2) ? gBh : gBl;
            const void* src = gp + r * 128 + c * KC + cc * 8;
            asm volatile("cp.async.cg.shared.global [%0], [%1], 16;"
                :: "r"(dst), "l"(src));
        }
        asm volatile("cp.async.commit_group;");
    };

    // ---- chunk compute: k=32 (2 k16 steps), 3-term bf16 split ----
    auto compute_chunk = [&](uint32_t setbase) {
#pragma unroll
        for (int kk = 0; kk < 2; ++kk) {
            uint32_t ah0[4], al0[4], ah1[4], al1[4];
            const uint32_t ab = sbase + setbase + aoff + kk * 32;
            ldsm4(ah0, ab);
            ldsm4(ah1, ab + 16 * ROWB);
            ldsm4(al0, ab + BUFB);
            ldsm4(al1, ab + BUFB + 16 * ROWB);
#pragma unroll
            for (int j2 = 0; j2 < 4; ++j2) {
                uint32_t bh[4], bl[4];
                const uint32_t bb = sbase + setbase + 2 * BUFB + boff
                                  + j2 * (16 * ROWB) + kk * 32;
                ldsm4(bh, bb);
                ldsm4(bl, bb + BUFB);
                float* c00 = acc + (2 * j2) * 4;
                float* c01 = acc + (2 * j2 + 1) * 4;
                float* c10 = acc + 32 + (2 * j2) * 4;
                float* c11 = acc + 32 + (2 * j2 + 1) * 4;
                mma16816(c00, ah0, bh[0], bh[1]);
                mma16816(c00, ah0, bl[0], bl[1]);
                mma16816(c00, al0, bh[0], bh[1]);
                mma16816(c01, ah0, bh[2], bh[3]);
                mma16816(c01, ah0, bl[2], bl[3]);
                mma16816(c01, al0, bh[2], bh[3]);
                mma16816(c10, ah1, bh[0], bh[1]);
                mma16816(c10, ah1, bl[0], bl[1]);
                mma16816(c10, al1, bh[0], bh[1]);
                mma16816(c11, ah1, bh[2], bh[3]);
                mma16816(c11, ah1, bl[2], bl[3]);
                mma16816(c11, al1, bh[2], bh[3]);
            }
        }
    };

    // ---- pipelined mainloop: 4 chunks, 2 buffer sets ----
    issue_chunk(0, 0);
    issue_chunk(1, SETB);
#pragma unroll
    for (int c = 0; c < 4; ++c) {
        if (c < 3) asm volatile("cp.async.wait_group 1;");
        else       asm volatile("cp.async.wait_group 0;");
        __syncthreads();                       // chunk c data visible to all
        compute_chunk((c & 1) ? SETB : 0);
        __syncthreads();                       // all reads of this set done
        if (c < 2) issue_chunk(c + 2, (c & 1) ? SETB : 0);
    }

    // ---- epilogue: acc-1 -> sM (fp32, stride 130) ----
    float* sM = reinterpret_cast<float*>(smem);
    {
        const int rr = lane >> 2;
        const int cb = (lane & 3) << 1;
#pragma unroll
        for (int mt = 0; mt < 2; ++mt) {
            const int r0 = 32 * mw + 16 * mt + rr;
#pragma unroll
            for (int n8 = 0; n8 < 8; ++n8) {
                const int col = 64 * nw + 8 * n8 + cb;
                float* c = acc + mt * 32 + n8 * 4;
                *reinterpret_cast<float2*>(&sM[r0 * SM_STRIDE + col])
                    = make_float2(c[0] - 1.0f, c[1] - 1.0f);
                *reinterpret_cast<float2*>(&sM[(r0 + 8) * SM_STRIDE + col])
                    = make_float2(c[2] - 1.0f, c[3] - 1.0f);
            }
        }
    }
    __syncthreads();

    // ---- PDE: single-warp register wavefront, no barriers ----
    // K[p][q] = K[p][q-1] + K[p-1][q] + K[p-1][q-1]*(M-1)[p-1][q-1], K[0][*]=K[*][0]=1
    // Lane r owns rows 4r+1..4r+4. shc(s) = neighbor cur3 pre-step = K[4r][s-1-4r];
    // shp(s) = K[4r][s-2-4r] = shc(s-1) -> carried register, ONE shfl per step.
    if (wid == 0) {
        const float* mp = sM + 516 * lane - 2;   // mp[129*i + s]
        const int p1 = 4 * lane + 1, p2 = p1 + 1, p3 = p1 + 2, p4 = p1 + 3;
        float cur0 = 1.f, cur1 = 1.f, cur2 = 1.f, cur3 = 1.f;
        float pr0 = 1.f, pr1 = 1.f, pr2 = 1.f;
        float shc_prev = 1.f;

        // phase A: s = 2..127 (guarded commits)
#pragma unroll 2
        for (int s = 2; s <= 127; ++s) {
            float shc = __shfl_up_sync(0xffffffffu, cur3, 1);
            if (lane == 0) shc = 1.f;
            const float shp = shc_prev;
            const float m0 = mp[s];
            const float m1 = mp[129 + s];
            const float m2 = mp[258 + s];
            const float m3 = mp[387 + s];
            const float v0 = cur0 + shc  + shp * m0;
            const float v1 = cur1 + cur0 + pr0 * m1;
            const float v2 = cur2 + cur1 + pr1 * m2;
            const float v3 = cur3 + cur2 + pr2 * m3;
            shc_prev = shc;
            if (s > p1) { pr0 = cur0; cur0 = v0; }
            if (s > p2) { pr1 = cur1; cur1 = v1; }
            if (s > p3) { pr2 = cur2; cur2 = v2; }
            if (s > p4) { cur3 = v3; }
        }
        // phase B: s = 128..254 (unguarded; post-completion garbage is harmless)
#pragma unroll 2
        for (int s = 128; s <= 254; ++s) {
            float shc = __shfl_up_sync(0xffffffffu, cur3, 1);
            if (lane == 0) shc = 1.f;
            const float shp = shc_prev;
            const float m0 = mp[s];
            const float m1 = mp[129 + s];
            const float m2 = mp[258 + s];
            const float m3 = mp[387 + s];
            const float v0 = cur0 + shc  + shp * m0;
            const float v1 = cur1 + cur0 + pr0 * m1;
            const float v2 = cur2 + cur1 + pr1 * m2;
            const float v3 = cur3 + cur2 + pr2 * m3;
            shc_prev = shc;
            pr0 = cur0; cur0 = v0;
            pr1 = cur1; cur1 = v1;
            pr2 = cur2; cur2 = v2;
            cur3 = v3;
        }
        // K[127][127] = row 127 (lane 31, i=2) update at s=254
        if (lane == 31) g_partials[bid] = w * cur2;
    }
    // warps 1..7 exit (only warp 0 reads sM now)
}

// ---------------- deterministic FP64 reduction ----------------
__global__ void sig_reduce_kernel(float* __restrict__ out) {
    __shared__ double sh[256];
    const int tid = threadIdx.x;
    double acc = 0.0;
    for (int i = tid; i < NP; i += 256) acc += (double)g_partials[i];
    sh[tid] = acc;
    __syncthreads();
    for (int s = 128; s > 0; s >>= 1) {
        if (tid < s) sh[tid] += sh[tid + s];
        __syncthreads();
    }
    if (tid == 0) out[0] = (float)(sh[0] * (1.0 / 4096.0));
}

extern "C" void kernel_launch(void* const* d_in, const int* in_sizes, int n_in,
                              void* d_out, int out_size) {
    const float* X = (const float*)d_in[0];
    const float* Y = (const float*)d_in[1];
    float* out = (float*)d_out;

    cudaFuncSetAttribute(sig_block_kernel,
                         cudaFuncAttributeMaxDynamicSharedMemorySize, SMEM_BYTES);

    sig_precompute_kernel<<<128, 256>>>(X, Y);
    sig_block_kernel<<<NP, 256, SMEM_BYTES>>>();
    sig_reduce_kernel<<<1, 256>>>(out);
}